// round 1
// baseline (speedup 1.0000x reference)
#include <cuda_runtime.h>

// ---------------------------------------------------------------------------
// GCN 2-layer forward:
//   h   = relu( D^-1/2 (A+I) D^-1/2 (x@W1) + b1 )
//   out =       D^-1/2 (A+I) D^-1/2 (h@W2) + b2
// Restructured:
//   y   = (x@W) * dinv[:,None]          (GEMM + row scale)
//   acc = y                             (self-loop folded into init)
//   acc[dst] += y[src]   for each edge  (pure scatter-add, no per-edge norm)
//   out = acc * dinv[:,None] + b        (epilogue; relu for layer 1)
// ---------------------------------------------------------------------------

#define NODES_MAX 100000
#define FEAT_IN   128
#define FEAT      64

__device__ float g_y  [(size_t)NODES_MAX * FEAT];
__device__ float g_acc[(size_t)NODES_MAX * FEAT];
__device__ float g_h  [(size_t)NODES_MAX * FEAT];
__device__ float g_dinv[NODES_MAX];
__device__ int   g_deg [NODES_MAX];
__device__ int   g_is64;

// ---------------------------------------------------------------------------
// Detect whether edge_index buffer is int64 (odd int32 words all zero) or int32.
// Values are in [0, 100000) so int64 high words are exactly 0.
// ---------------------------------------------------------------------------
__global__ void detect_kernel(const int* __restrict__ ei) {
    int v = ei[2 * threadIdx.x + 1];
    unsigned b = __ballot_sync(0xffffffffu, v != 0);
    if (threadIdx.x == 0) g_is64 = (b == 0u) ? 1 : 0;
}

__global__ void deg_init_kernel(int* __restrict__ deg, int n) {
    int i = blockIdx.x * blockDim.x + threadIdx.x;
    if (i < n) deg[i] = 1;  // self-loop
}

__global__ void deg_count_kernel(const int* __restrict__ ei, int* __restrict__ deg, int E) {
    int e = blockIdx.x * blockDim.x + threadIdx.x;
    if (e >= E) return;
    long long pos = (long long)E + e;           // dst row of edge_index
    int d = g_is64 ? ei[2 * pos] : ei[pos];
    atomicAdd(&deg[d], 1);
}

__global__ void dinv_kernel(const int* __restrict__ deg, float* __restrict__ dinv, int n) {
    int i = blockIdx.x * blockDim.x + threadIdx.x;
    if (i < n) dinv[i] = rsqrtf((float)deg[i]);
}

// ---------------------------------------------------------------------------
// Tiled GEMM + row-scale:  y[i][c] = acc[i][c] = (sum_k X[i][k] W[k][c]) * dinv[i]
// Block tile: 128 nodes x 64 channels, K chunked by 32.
// Thread tile: 8 nodes x 4 channels (256 threads).
// ---------------------------------------------------------------------------
template <int K>
__global__ __launch_bounds__(256) void gemm_scale_kernel(
    const float* __restrict__ X, const float* __restrict__ W,
    const float* __restrict__ dinv,
    float* __restrict__ y, float* __restrict__ acc, int n)
{
    constexpr int BN = 128;
    constexpr int KC = 32;
    __shared__ __align__(16) float Xs[BN][KC];
    __shared__ __align__(16) float Ws[KC][64];

    int tid = threadIdx.x;
    int cg  = tid & 15;   // channel group: channels [cg*4, cg*4+4)
    int ng  = tid >> 4;   // node group: nodes ng + 16*i, i in [0,8)
    int node0 = blockIdx.x * BN;

    float4 accv[8];
#pragma unroll
    for (int i = 0; i < 8; i++) accv[i] = make_float4(0.f, 0.f, 0.f, 0.f);

    for (int kc = 0; kc < K; kc += KC) {
        // Load X chunk: 128 x 32 floats = 1024 float4, 4 per thread (coalesced).
#pragma unroll
        for (int l = 0; l < 4; l++) {
            int fi = tid + l * 256;
            int r  = fi >> 3;            // row (node within block)
            int c  = (fi & 7) << 2;      // col within chunk
            int node = node0 + r;
            float4 v = make_float4(0.f, 0.f, 0.f, 0.f);
            if (node < n) v = *(const float4*)(X + (size_t)node * K + kc + c);
            *(float4*)(&Xs[r][c]) = v;
        }
        // Load W chunk: 32 x 64 floats = 512 float4, 2 per thread.
#pragma unroll
        for (int l = 0; l < 2; l++) {
            int fi = tid + l * 256;
            int r  = fi >> 4;
            int c  = (fi & 15) << 2;
            *(float4*)(&Ws[r][c]) = *(const float4*)(W + (size_t)(kc + r) * 64 + c);
        }
        __syncthreads();

#pragma unroll
        for (int k4 = 0; k4 < KC; k4 += 4) {
            float4 wr[4];
#pragma unroll
            for (int kk = 0; kk < 4; kk++)
                wr[kk] = *(float4*)(&Ws[k4 + kk][cg << 2]);
#pragma unroll
            for (int i = 0; i < 8; i++) {
                float4 xq = *(float4*)(&Xs[ng + 16 * i][k4]);
                accv[i].x = fmaf(xq.x, wr[0].x, accv[i].x);
                accv[i].y = fmaf(xq.x, wr[0].y, accv[i].y);
                accv[i].z = fmaf(xq.x, wr[0].z, accv[i].z);
                accv[i].w = fmaf(xq.x, wr[0].w, accv[i].w);
                accv[i].x = fmaf(xq.y, wr[1].x, accv[i].x);
                accv[i].y = fmaf(xq.y, wr[1].y, accv[i].y);
                accv[i].z = fmaf(xq.y, wr[1].z, accv[i].z);
                accv[i].w = fmaf(xq.y, wr[1].w, accv[i].w);
                accv[i].x = fmaf(xq.z, wr[2].x, accv[i].x);
                accv[i].y = fmaf(xq.z, wr[2].y, accv[i].y);
                accv[i].z = fmaf(xq.z, wr[2].z, accv[i].z);
                accv[i].w = fmaf(xq.z, wr[2].w, accv[i].w);
                accv[i].x = fmaf(xq.w, wr[3].x, accv[i].x);
                accv[i].y = fmaf(xq.w, wr[3].y, accv[i].y);
                accv[i].z = fmaf(xq.w, wr[3].z, accv[i].z);
                accv[i].w = fmaf(xq.w, wr[3].w, accv[i].w);
            }
        }
        __syncthreads();
    }

#pragma unroll
    for (int i = 0; i < 8; i++) {
        int node = node0 + ng + 16 * i;
        if (node < n) {
            float di = dinv[node];
            float4 v = accv[i];
            v.x *= di; v.y *= di; v.z *= di; v.w *= di;
            size_t off = (size_t)node * 64 + (cg << 2);
            *(float4*)(y + off)   = v;
            *(float4*)(acc + off) = v;   // self-loop contribution pre-folded
        }
    }
}

// ---------------------------------------------------------------------------
// Edge scatter: acc[dst] += y[src], 64 floats/edge, 16 threads/edge, float4 each.
// Vectorized fire-and-forget atomic (red.global.add.v4.f32, sm_90+).
// ---------------------------------------------------------------------------
__global__ __launch_bounds__(256) void scatter_kernel(
    const int* __restrict__ ei,
    const float4* __restrict__ y, float4* __restrict__ acc, int E)
{
    long long idx = (long long)blockIdx.x * blockDim.x + threadIdx.x;
    long long e = idx >> 4;
    if (e >= E) return;
    int c = (int)(idx & 15);

    long long s, d;
    if (g_is64) {
        s = ei[2 * e];
        d = ei[2 * ((long long)E + e)];
    } else {
        s = ei[e];
        d = ei[(long long)E + e];
    }
    float4 v = y[s * 16 + c];
    float4* p = acc + d * 16 + c;
    asm volatile("red.global.add.v4.f32 [%0], {%1, %2, %3, %4};"
                 :: "l"(p), "f"(v.x), "f"(v.y), "f"(v.z), "f"(v.w)
                 : "memory");
}

// ---------------------------------------------------------------------------
// Epilogue: out[i][c] = (relu)( acc[i][c] * dinv[i] + b[c] )
// ---------------------------------------------------------------------------
template <bool RELU>
__global__ __launch_bounds__(256) void epi_kernel(
    const float4* __restrict__ acc, const float* __restrict__ dinv,
    const float4* __restrict__ b, float4* __restrict__ out, int n)
{
    int idx = blockIdx.x * blockDim.x + threadIdx.x;
    if (idx >= n * 16) return;
    int node = idx >> 4;
    int c    = idx & 15;
    float di = dinv[node];
    float4 a = acc[idx];
    float4 bb = b[c];
    float4 v;
    v.x = fmaf(a.x, di, bb.x);
    v.y = fmaf(a.y, di, bb.y);
    v.z = fmaf(a.z, di, bb.z);
    v.w = fmaf(a.w, di, bb.w);
    if (RELU) {
        v.x = fmaxf(v.x, 0.f);
        v.y = fmaxf(v.y, 0.f);
        v.z = fmaxf(v.z, 0.f);
        v.w = fmaxf(v.w, 0.f);
    }
    out[idx] = v;
}

// ---------------------------------------------------------------------------
extern "C" void kernel_launch(void* const* d_in, const int* in_sizes, int n_in,
                              void* d_out, int out_size)
{
    const float* x  = (const float*)d_in[0];
    const int*   ei = (const int*)d_in[1];   // int32 or int64 (auto-detected)
    const float* W1 = (const float*)d_in[2];
    const float* b1 = (const float*)d_in[3];
    const float* W2 = (const float*)d_in[4];
    const float* b2 = (const float*)d_in[5];

    int n = in_sizes[0] / FEAT_IN;   // 100000
    int E = in_sizes[1] / 2;         // 1600000 (element count halves to E either dtype)

    float *y, *acc, *h, *dinv;
    int *deg;
    cudaGetSymbolAddress((void**)&y,    g_y);
    cudaGetSymbolAddress((void**)&acc,  g_acc);
    cudaGetSymbolAddress((void**)&h,    g_h);
    cudaGetSymbolAddress((void**)&dinv, g_dinv);
    cudaGetSymbolAddress((void**)&deg,  g_deg);

    const int T = 256;

    detect_kernel<<<1, 32>>>(ei);
    deg_init_kernel<<<(n + T - 1) / T, T>>>(deg, n);
    deg_count_kernel<<<(E + T - 1) / T, T>>>(ei, deg, E);
    dinv_kernel<<<(n + T - 1) / T, T>>>(deg, dinv, n);

    long long sth = (long long)E * 16;
    int sblocks = (int)((sth + T - 1) / T);
    int eblocks = (n * 16 + T - 1) / T;

    // ---- Layer 1 ----
    gemm_scale_kernel<128><<<(n + 127) / 128, 256>>>(x, W1, dinv, y, acc, n);
    scatter_kernel<<<sblocks, T>>>(ei, (const float4*)y, (float4*)acc, E);
    epi_kernel<true><<<eblocks, T>>>((const float4*)acc, dinv, (const float4*)b1,
                                     (float4*)h, n);

    // ---- Layer 2 ----
    gemm_scale_kernel<64><<<(n + 127) / 128, 256>>>(h, W2, dinv, y, acc, n);
    scatter_kernel<<<sblocks, T>>>(ei, (const float4*)y, (float4*)acc, E);
    epi_kernel<false><<<eblocks, T>>>((const float4*)acc, dinv, (const float4*)b2,
                                      (float4*)d_out, n);
}

// round 2
// speedup vs baseline: 1.6852x; 1.6852x over previous
#include <cuda_runtime.h>

// ---------------------------------------------------------------------------
// GCN 2-layer forward, pull-based (CSR gather, atomic-free aggregation):
//   y   = (x@W) * dinv[:,None]                      (GEMM + row scale)
//   out[d] = (y[d] + sum_{e: dst=d} y[src_e]) * dinv[d] + b   (+relu L1)
// CSR by dst is built once per call and reused by both layers.
// ---------------------------------------------------------------------------

#define NODES_MAX 100000
#define EDGES_MAX 1600000
#define FEAT_IN   128
#define FEAT      64

__device__ float g_y   [(size_t)NODES_MAX * FEAT];
__device__ float g_h   [(size_t)NODES_MAX * FEAT];
__device__ float g_dinv[NODES_MAX];
__device__ int   g_deg [NODES_MAX];          // in-degree (edges only)
__device__ int   g_off [NODES_MAX + 1];      // CSR row offsets
__device__ int   g_cur [NODES_MAX];          // fill cursors
__device__ int   g_csr [EDGES_MAX];          // src ids grouped by dst
__device__ int   g_bsum[512];                // block sums for scan
__device__ int   g_is64;

// ---------------------------------------------------------------------------
__global__ void detect_kernel(const int* __restrict__ ei) {
    int v = ei[2 * threadIdx.x + 1];
    unsigned b = __ballot_sync(0xffffffffu, v != 0);
    if (threadIdx.x == 0) g_is64 = (b == 0u) ? 1 : 0;
}

__global__ void zero_deg_kernel(int* __restrict__ deg, int n) {
    int i = blockIdx.x * blockDim.x + threadIdx.x;
    if (i < n) deg[i] = 0;
}

__global__ void deg_count_kernel(const int* __restrict__ ei, int* __restrict__ deg, int E) {
    int e = blockIdx.x * blockDim.x + threadIdx.x;
    if (e >= E) return;
    long long pos = (long long)E + e;           // dst row
    int d = g_is64 ? ei[2 * pos] : ei[pos];
    atomicAdd(&deg[d], 1);
}

__global__ void dinv_kernel(const int* __restrict__ deg, float* __restrict__ dinv, int n) {
    int i = blockIdx.x * blockDim.x + threadIdx.x;
    if (i < n) dinv[i] = rsqrtf((float)(deg[i] + 1));  // +1 self-loop
}

// ---------------------------------------------------------------------------
// Block-wide exclusive scan helper (blockDim.x <= 1024, multiple of 32).
// Returns exclusive prefix; *total gets the block-wide sum (valid after call).
// ---------------------------------------------------------------------------
__device__ __forceinline__ int block_exscan(int v, int* total) {
    __shared__ int wsum[32];
    int lane = threadIdx.x & 31, wid = threadIdx.x >> 5;
    int nw = blockDim.x >> 5;
    int inc = v;
#pragma unroll
    for (int o = 1; o < 32; o <<= 1) {
        int t = __shfl_up_sync(0xffffffffu, inc, o);
        if (lane >= o) inc += t;
    }
    if (lane == 31) wsum[wid] = inc;
    __syncthreads();
    if (wid == 0) {
        int ws = (lane < nw) ? wsum[lane] : 0;
#pragma unroll
        for (int o = 1; o < 32; o <<= 1) {
            int t = __shfl_up_sync(0xffffffffu, ws, o);
            if (lane >= o) ws += t;
        }
        wsum[lane] = ws;   // inclusive warp sums
    }
    __syncthreads();
    int woff = (wid == 0) ? 0 : wsum[wid - 1];
    *total = wsum[nw - 1];
    return woff + inc - v;
}

__global__ void scan1_kernel(const int* __restrict__ deg, int* __restrict__ off,
                             int* __restrict__ bsum, int n) {
    int i = blockIdx.x * blockDim.x + threadIdx.x;
    int v = (i < n) ? deg[i] : 0;
    int tot;
    int ex = block_exscan(v, &tot);
    if (i < n) off[i] = ex;
    if (threadIdx.x == 0) bsum[blockIdx.x] = tot;
}

__global__ void scan2_kernel(int* __restrict__ bsum, int nb) {
    int i = threadIdx.x;
    int v = (i < nb) ? bsum[i] : 0;
    int tot;
    int ex = block_exscan(v, &tot);
    if (i < nb) bsum[i] = ex;
}

__global__ void scan3_kernel(int* __restrict__ off, const int* __restrict__ bsum,
                             int* __restrict__ cur, int n, int E) {
    int i = blockIdx.x * blockDim.x + threadIdx.x;
    if (i < n) {
        int o = off[i] + bsum[blockIdx.x];
        off[i] = o;
        cur[i] = o;
    }
    if (i == 0) off[n] = E;
}

__global__ void fill_kernel(const int* __restrict__ ei, int* __restrict__ cur,
                            int* __restrict__ csr, int E) {
    int e = blockIdx.x * blockDim.x + threadIdx.x;
    if (e >= E) return;
    int s, d;
    if (g_is64) {
        s = ei[2 * (long long)e];
        d = ei[2 * ((long long)E + e)];
    } else {
        s = ei[e];
        d = ei[(long long)E + e];
    }
    int pos = atomicAdd(&cur[d], 1);
    csr[pos] = s;
}

// ---------------------------------------------------------------------------
// Tiled GEMM + row-scale: y[i][c] = (sum_k X[i][k] W[k][c]) * dinv[i]
// ---------------------------------------------------------------------------
template <int K>
__global__ __launch_bounds__(256) void gemm_scale_kernel(
    const float* __restrict__ X, const float* __restrict__ W,
    const float* __restrict__ dinv, float* __restrict__ y, int n)
{
    constexpr int BN = 128;
    constexpr int KC = 32;
    __shared__ __align__(16) float Xs[BN][KC];
    __shared__ __align__(16) float Ws[KC][64];

    int tid = threadIdx.x;
    int cg  = tid & 15;
    int ng  = tid >> 4;
    int node0 = blockIdx.x * BN;

    float4 accv[8];
#pragma unroll
    for (int i = 0; i < 8; i++) accv[i] = make_float4(0.f, 0.f, 0.f, 0.f);

    for (int kc = 0; kc < K; kc += KC) {
#pragma unroll
        for (int l = 0; l < 4; l++) {
            int fi = tid + l * 256;
            int r  = fi >> 3;
            int c  = (fi & 7) << 2;
            int node = node0 + r;
            float4 v = make_float4(0.f, 0.f, 0.f, 0.f);
            if (node < n) v = *(const float4*)(X + (size_t)node * K + kc + c);
            *(float4*)(&Xs[r][c]) = v;
        }
#pragma unroll
        for (int l = 0; l < 2; l++) {
            int fi = tid + l * 256;
            int r  = fi >> 4;
            int c  = (fi & 15) << 2;
            *(float4*)(&Ws[r][c]) = *(const float4*)(W + (size_t)(kc + r) * 64 + c);
        }
        __syncthreads();

#pragma unroll
        for (int k4 = 0; k4 < KC; k4 += 4) {
            float4 wr[4];
#pragma unroll
            for (int kk = 0; kk < 4; kk++)
                wr[kk] = *(float4*)(&Ws[k4 + kk][cg << 2]);
#pragma unroll
            for (int i = 0; i < 8; i++) {
                float4 xq = *(float4*)(&Xs[ng + 16 * i][k4]);
                accv[i].x = fmaf(xq.x, wr[0].x, accv[i].x);
                accv[i].y = fmaf(xq.x, wr[0].y, accv[i].y);
                accv[i].z = fmaf(xq.x, wr[0].z, accv[i].z);
                accv[i].w = fmaf(xq.x, wr[0].w, accv[i].w);
                accv[i].x = fmaf(xq.y, wr[1].x, accv[i].x);
                accv[i].y = fmaf(xq.y, wr[1].y, accv[i].y);
                accv[i].z = fmaf(xq.y, wr[1].z, accv[i].z);
                accv[i].w = fmaf(xq.y, wr[1].w, accv[i].w);
                accv[i].x = fmaf(xq.z, wr[2].x, accv[i].x);
                accv[i].y = fmaf(xq.z, wr[2].y, accv[i].y);
                accv[i].z = fmaf(xq.z, wr[2].z, accv[i].z);
                accv[i].w = fmaf(xq.z, wr[2].w, accv[i].w);
                accv[i].x = fmaf(xq.w, wr[3].x, accv[i].x);
                accv[i].y = fmaf(xq.w, wr[3].y, accv[i].y);
                accv[i].z = fmaf(xq.w, wr[3].z, accv[i].z);
                accv[i].w = fmaf(xq.w, wr[3].w, accv[i].w);
            }
        }
        __syncthreads();
    }

#pragma unroll
    for (int i = 0; i < 8; i++) {
        int node = node0 + ng + 16 * i;
        if (node < n) {
            float di = dinv[node];
            float4 v = accv[i];
            v.x *= di; v.y *= di; v.z *= di; v.w *= di;
            *(float4*)(y + (size_t)node * 64 + (cg << 2)) = v;
        }
    }
}

// ---------------------------------------------------------------------------
// Fused gather + epilogue: 16 threads per node, float4 per thread.
// out[d] = (relu)( (y[d] + sum_{j in csr row d} y[csr[j]]) * dinv[d] + b )
// Edge loop unrolled by 2 with index prefetch for MLP.
// ---------------------------------------------------------------------------
template <bool RELU>
__global__ __launch_bounds__(256) void gather_kernel(
    const int* __restrict__ off, const int* __restrict__ csr,
    const float4* __restrict__ y, const float* __restrict__ dinv,
    const float4* __restrict__ b, float4* __restrict__ out, int n)
{
    int idx = blockIdx.x * blockDim.x + threadIdx.x;
    int node = idx >> 4;
    if (node >= n) return;
    int c = idx & 15;

    int j   = off[node];
    int end = off[node + 1];

    float4 acc = y[(size_t)node * 16 + c];   // self-loop

    // unroll-2 main loop
    for (; j + 2 <= end; j += 2) {
        int s0 = csr[j];
        int s1 = csr[j + 1];
        float4 v0 = y[(size_t)s0 * 16 + c];
        float4 v1 = y[(size_t)s1 * 16 + c];
        acc.x += v0.x + v1.x;
        acc.y += v0.y + v1.y;
        acc.z += v0.z + v1.z;
        acc.w += v0.w + v1.w;
    }
    if (j < end) {
        int s0 = csr[j];
        float4 v0 = y[(size_t)s0 * 16 + c];
        acc.x += v0.x; acc.y += v0.y; acc.z += v0.z; acc.w += v0.w;
    }

    float di = dinv[node];
    float4 bb = b[c];
    float4 r;
    r.x = fmaf(acc.x, di, bb.x);
    r.y = fmaf(acc.y, di, bb.y);
    r.z = fmaf(acc.z, di, bb.z);
    r.w = fmaf(acc.w, di, bb.w);
    if (RELU) {
        r.x = fmaxf(r.x, 0.f);
        r.y = fmaxf(r.y, 0.f);
        r.z = fmaxf(r.z, 0.f);
        r.w = fmaxf(r.w, 0.f);
    }
    out[idx] = r;
}

// ---------------------------------------------------------------------------
extern "C" void kernel_launch(void* const* d_in, const int* in_sizes, int n_in,
                              void* d_out, int out_size)
{
    const float* x  = (const float*)d_in[0];
    const int*   ei = (const int*)d_in[1];   // int32 or int64 (auto-detected)
    const float* W1 = (const float*)d_in[2];
    const float* b1 = (const float*)d_in[3];
    const float* W2 = (const float*)d_in[4];
    const float* b2 = (const float*)d_in[5];

    int n = in_sizes[0] / FEAT_IN;   // 100000
    int E = in_sizes[1] / 2;         // 1600000

    float *y, *h, *dinv;
    int *deg, *off, *cur, *csr, *bsum;
    cudaGetSymbolAddress((void**)&y,    g_y);
    cudaGetSymbolAddress((void**)&h,    g_h);
    cudaGetSymbolAddress((void**)&dinv, g_dinv);
    cudaGetSymbolAddress((void**)&deg,  g_deg);
    cudaGetSymbolAddress((void**)&off,  g_off);
    cudaGetSymbolAddress((void**)&cur,  g_cur);
    cudaGetSymbolAddress((void**)&csr,  g_csr);
    cudaGetSymbolAddress((void**)&bsum, g_bsum);

    const int T = 256;
    int nb = (n + T - 1) / T;   // 391
    int eb = (E + T - 1) / T;

    // ---- CSR build (once, reused by both layers) ----
    detect_kernel<<<1, 32>>>(ei);
    zero_deg_kernel<<<nb, T>>>(deg, n);
    deg_count_kernel<<<eb, T>>>(ei, deg, E);
    dinv_kernel<<<nb, T>>>(deg, dinv, n);
    scan1_kernel<<<nb, T>>>(deg, off, bsum, n);
    scan2_kernel<<<1, 512>>>(bsum, nb);
    scan3_kernel<<<nb, T>>>(off, bsum, cur, n, E);
    fill_kernel<<<eb, T>>>(ei, cur, csr, E);

    int gb = (n * 16 + T - 1) / T;

    // ---- Layer 1 ----
    gemm_scale_kernel<128><<<(n + 127) / 128, 256>>>(x, W1, dinv, y, n);
    gather_kernel<true><<<gb, T>>>(off, csr, (const float4*)y, dinv,
                                   (const float4*)b1, (float4*)h, n);

    // ---- Layer 2 ----
    gemm_scale_kernel<64><<<(n + 127) / 128, 256>>>(h, W2, dinv, y, n);
    gather_kernel<false><<<gb, T>>>(off, csr, (const float4*)y, dinv,
                                    (const float4*)b2, (float4*)d_out, n);
}